// round 16
// baseline (speedup 1.0000x reference)
#include <cuda_runtime.h>
#include <cuda_bf16.h>
#include <cstdint>

#define NB 8
#define NT 2048
#define ND 256
#define BT (NB*NT)
#define CCAP 12

// ================= scratch (static device globals; no allocation) =================
__device__ __align__(16) float g_vb1[BT*ND];
__device__ __align__(16) float g_ab2[BT*ND];
__device__ __align__(16) __nv_bfloat16 g_vb2h[BT*ND];
__device__ __align__(16) __nv_bfloat16 g_vb2l[BT*ND];
__device__ __align__(16) __nv_bfloat16 g_ab1h[BT*ND];
__device__ __align__(16) __nv_bfloat16 g_ab1l[BT*ND];
__device__ __align__(16) __nv_bfloat16 g_vfh[BT*ND];
__device__ __align__(16) __nv_bfloat16 g_vfl[BT*ND];
__device__ __align__(16) __nv_bfloat16 g_afh[BT*ND];
__device__ __align__(16) __nv_bfloat16 g_afl[BT*ND];
__device__ __align__(16) __nv_bfloat16 g_wth[4*ND*ND];
__device__ __align__(16) __nv_bfloat16 g_wtl[4*ND*ND];
__device__ float g_beta[(size_t)NB*NT*NT];
__device__ float g_rowpart[16*NB*NT];
__device__ float g_colpart[16*NB*NT];
__device__ float g_rowsum[NB*NT];
__device__ float g_icolsum[NB*NT];
__device__ float g_apos[BT*ND];
__device__ int   g_ccnt[NB*NT];
__device__ float g_cval[(size_t)NB*NT*CCAP];
__device__ int   g_cv[(size_t)NB*NT*CCAP];

// ================= PTX helpers =================
__device__ __forceinline__ uint32_t smem_u32(const void* p) {
    uint32_t a;
    asm("{ .reg .u64 t; cvta.to.shared.u64 t, %1; cvt.u32.u64 %0, t; }" : "=r"(a) : "l"(p));
    return a;
}
#define LDMX4(r, addr) \
    asm volatile("ldmatrix.sync.aligned.m8n8.x4.shared.b16 {%0,%1,%2,%3}, [%4];" \
        : "=r"((r)[0]), "=r"((r)[1]), "=r"((r)[2]), "=r"((r)[3]) : "r"(addr))
#define MMA_BF16(d, a, b) \
    asm volatile("mma.sync.aligned.m16n8k16.row.col.f32.bf16.bf16.f32 " \
        "{%0,%1,%2,%3}, {%4,%5,%6,%7}, {%8,%9}, {%0,%1,%2,%3};" \
        : "+f"((d)[0]), "+f"((d)[1]), "+f"((d)[2]), "+f"((d)[3]) \
        : "r"((a)[0]), "r"((a)[1]), "r"((a)[2]), "r"((a)[3]), "r"((b)[0]), "r"((b)[1]))
#define CPA16(dst, src) \
    asm volatile("cp.async.cg.shared.global [%0], [%1], 16;" :: "r"(dst), "l"(src) : "memory")
#define CPA_COMMIT() asm volatile("cp.async.commit_group;" ::: "memory")
#define CPA_WAIT0()  asm volatile("cp.async.wait_group 0;" ::: "memory")

#define ROWB 80
#define ARR_SZ (128*ROWB)
#define OFF_AH 0
#define OFF_AL (1*ARR_SZ)
#define OFF_BH (2*ARR_SZ)
#define OFF_BL (3*ARR_SZ)
#define BUF_SZ (4*ARR_SZ)
#define SMEM_S1 (2*BUF_SZ)   // 81920

// ================= HMMA GEMM core (locked: load-all-fragments-then-MMA) =================
__device__ __forceinline__ void gemm128(
    const uint4* __restrict__ Ah, const uint4* __restrict__ Al,
    const uint4* __restrict__ Bh, const uint4* __restrict__ Bl,
    char* smem, float acc[4][4][4], int tid)
{
    const int lane = tid & 31, wid = tid >> 5;
    const int wm = wid >> 2, wn = wid & 3;
    uint32_t sb = smem_u32(smem);
    const int row0 = tid >> 2, q = tid & 3;
    auto COPY = [&](int kc, int s) {
        uint32_t buf = sb + s * BUF_SZ;
#pragma unroll
        for (int i = 0; i < 2; i++) {
            int r = row0 + i * 64;
            int gi = r * 32 + kc * 4 + q;
            uint32_t so = (uint32_t)r * ROWB + q * 16;
            CPA16(buf + OFF_AH + so, Ah + gi);
            CPA16(buf + OFF_AL + so, Al + gi);
            CPA16(buf + OFF_BH + so, Bh + gi);
            CPA16(buf + OFF_BL + so, Bl + gi);
        }
        CPA_COMMIT();
    };
    COPY(0, 0);
    const int t = lane >> 3, rr = lane & 7;
    uint32_t aoff = sb + (uint32_t)(wm * 64 + (t & 1) * 8 + rr) * ROWB + (t >> 1) * 16;
    uint32_t boff = sb + (uint32_t)(wn * 32 + (t >> 1) * 8 + rr) * ROWB + (t & 1) * 16;
    for (int kc = 0; kc < 8; kc++) {
        CPA_WAIT0();
        __syncthreads();
        if (kc < 7) COPY(kc + 1, (kc + 1) & 1);
        uint32_t bufb = (kc & 1) ? BUF_SZ : 0;
#pragma unroll
        for (int ks = 0; ks < 2; ks++) {
            uint32_t afh[4][4], afl[4][4], bh4[2][4], bl4[2][4];
#pragma unroll
            for (int mi = 0; mi < 4; mi++) {
                uint32_t ad = aoff + bufb + mi * (16 * ROWB) + ks * 32;
                LDMX4(afh[mi], ad + OFF_AH);
                LDMX4(afl[mi], ad + OFF_AL);
            }
#pragma unroll
            for (int n2 = 0; n2 < 2; n2++) {
                uint32_t bd = boff + bufb + n2 * (16 * ROWB) + ks * 32;
                LDMX4(bh4[n2], bd + OFF_BH);
                LDMX4(bl4[n2], bd + OFF_BL);
            }
#pragma unroll
            for (int mi = 0; mi < 4; mi++)
#pragma unroll
                for (int ni = 0; ni < 4; ni++)
                    MMA_BF16(acc[mi][ni], afh[mi], &bh4[ni >> 1][(ni & 1) * 2]);
#pragma unroll
            for (int mi = 0; mi < 4; mi++)
#pragma unroll
                for (int ni = 0; ni < 4; ni++)
                    MMA_BF16(acc[mi][ni], afh[mi], &bl4[ni >> 1][(ni & 1) * 2]);
#pragma unroll
            for (int mi = 0; mi < 4; mi++)
#pragma unroll
                for (int ni = 0; ni < 4; ni++)
                    MMA_BF16(acc[mi][ni], afl[mi], &bh4[ni >> 1][(ni & 1) * 2]);
        }
    }
    __syncthreads();
}

// ================= conversions (merged inputs + weights) =================
__device__ __forceinline__ void split4(float4 v, uint2& hi, uint2& lo) {
    __nv_bfloat16 h0 = __float2bfloat16(v.x), h1 = __float2bfloat16(v.y);
    __nv_bfloat16 h2 = __float2bfloat16(v.z), h3 = __float2bfloat16(v.w);
    __nv_bfloat16 l0 = __float2bfloat16(v.x - __bfloat162float(h0));
    __nv_bfloat16 l1 = __float2bfloat16(v.y - __bfloat162float(h1));
    __nv_bfloat16 l2 = __float2bfloat16(v.z - __bfloat162float(h2));
    __nv_bfloat16 l3 = __float2bfloat16(v.w - __bfloat162float(h3));
    hi.x = (uint32_t)*(uint16_t*)&h0 | ((uint32_t)*(uint16_t*)&h1 << 16);
    hi.y = (uint32_t)*(uint16_t*)&h2 | ((uint32_t)*(uint16_t*)&h3 << 16);
    lo.x = (uint32_t)*(uint16_t*)&l0 | ((uint32_t)*(uint16_t*)&l1 << 16);
    lo.y = (uint32_t)*(uint16_t*)&l2 | ((uint32_t)*(uint16_t*)&l3 << 16);
}

__global__ __launch_bounds__(256) void k_conv(const float4* __restrict__ vf, const float4* __restrict__ af,
                                              const float* __restrict__ W0, const float* __restrict__ W1,
                                              const float* __restrict__ W2, const float* __restrict__ W3) {
    int blk = blockIdx.x;
    if (blk < BT * ND / 4 / 256) {
        int i = blk * 256 + threadIdx.x;
        uint2 h, l;
        split4(vf[i], h, l);
        ((uint2*)g_vfh)[i] = h; ((uint2*)g_vfl)[i] = l;
        split4(af[i], h, l);
        ((uint2*)g_afh)[i] = h; ((uint2*)g_afl)[i] = l;
    } else {
        int wb = blk - BT * ND / 4 / 256;
        int z = wb >> 8;
        int lin = (wb & 255) * 256 + threadIdx.x;
        const float* W = (z == 0) ? W0 : (z == 1) ? W1 : (z == 2) ? W2 : W3;
        int k = lin & 255, n = lin >> 8;
        float v = W[k * 256 + n];
        __nv_bfloat16 h = __float2bfloat16(v);
        __nv_bfloat16 l = __float2bfloat16(v - __bfloat162float(h));
        g_wth[z * 65536 + n * 256 + k] = h;
        g_wtl[z * 65536 + n * 256 + k] = l;
    }
}

// ================= stage 1a: z=1 (vb2) and z=2 (ab1) GEMMs + relu + bf16 split =================
__global__ __launch_bounds__(256, 2) void k_hmma_s1() {
    extern __shared__ char smem[];
    int tid = threadIdx.x;
    int nx = blockIdx.x, mt = blockIdx.y, z = blockIdx.z + 1;   // z in {1,2}
    size_t arow = (size_t)mt * 128;
    const uint4* Ah = (const uint4*)((z == 1) ? g_vfh : g_afh) + arow * 32;
    const uint4* Al = (const uint4*)((z == 1) ? g_vfl : g_afl) + arow * 32;
    const uint4* Bh = (const uint4*)g_wth + ((size_t)z * 256 + nx * 128) * 32;
    const uint4* Bl = (const uint4*)g_wtl + ((size_t)z * 256 + nx * 128) * 32;
    float acc[4][4][4] = {};
    gemm128(Ah, Al, Bh, Bl, smem, acc, tid);

    int lane = tid & 31, wid = tid >> 5, wm = wid >> 2, wn = wid & 3;
    int g = lane >> 2, tg = lane & 3;
    __nv_bfloat16* Yh = (z == 1) ? g_vb2h : g_ab1h;
    __nv_bfloat16* Yl = (z == 1) ? g_vb2l : g_ab1l;
#pragma unroll
    for (int mi = 0; mi < 4; mi++)
#pragma unroll
        for (int h = 0; h < 2; h++) {
            size_t row = arow + wm * 64 + mi * 16 + g + h * 8;
#pragma unroll
            for (int ni = 0; ni < 4; ni++) {
                int col = nx * 128 + wn * 32 + ni * 8 + tg * 2;
                float d0 = fmaxf(acc[mi][ni][h * 2 + 0], 0.f);
                float d1 = fmaxf(acc[mi][ni][h * 2 + 1], 0.f);
                __nv_bfloat16 h0 = __float2bfloat16(d0), h1 = __float2bfloat16(d1);
                __nv_bfloat16 l0 = __float2bfloat16(d0 - __bfloat162float(h0));
                __nv_bfloat16 l1 = __float2bfloat16(d1 - __bfloat162float(h1));
                *(uint32_t*)&Yh[row * ND + col] =
                    (uint32_t)*(uint16_t*)&h0 | ((uint32_t)*(uint16_t*)&h1 << 16);
                *(uint32_t*)&Yl[row * ND + col] =
                    (uint32_t)*(uint16_t*)&l0 | ((uint32_t)*(uint16_t*)&l1 << 16);
            }
        }
}

// ================= fused: beta GEMM (blocks 0..2047) + s1 z=0/3 GEMMs (blocks 2048..2559) =================
__global__ __launch_bounds__(256, 2) void k_fused() {
    extern __shared__ char smem[];
    int tid = threadIdx.x;
    int blk = blockIdx.x;
    int lane = tid & 31, wid = tid >> 5, wm = wid >> 2, wn = wid & 3;
    int g = lane >> 2, tg = lane & 3;

    if (blk < 2048) {
        int nt = blk & 15, mt = (blk >> 4) & 15, b = blk >> 8;
        size_t arow = (size_t)b * NT + mt * 128;
        size_t brow = (size_t)b * NT + nt * 128;
        const uint4* Ah = (const uint4*)g_vb2h + arow * 32;
        const uint4* Al = (const uint4*)g_vb2l + arow * 32;
        const uint4* Bh = (const uint4*)g_ab1h + brow * 32;
        const uint4* Bl = (const uint4*)g_ab1l + brow * 32;
        float acc[4][4][4] = {};
        gemm128(Ah, Al, Bh, Bl, smem, acc, tid);

        float* rowacc = (float*)smem;
        float* colacc = (float*)smem + 512;
        const float sc = 0.0625f;
        float* Bo = g_beta + arow * NT + nt * 128;
        float rs[4][2] = {}, cs[4][2] = {};
#pragma unroll
        for (int mi = 0; mi < 4; mi++) {
            int r0 = wm * 64 + mi * 16 + g;
#pragma unroll
            for (int ni = 0; ni < 4; ni++) {
                int c = wn * 32 + ni * 8 + tg * 2;
                float d0 = fmaxf(acc[mi][ni][0] * sc, 0.f);
                float d1 = fmaxf(acc[mi][ni][1] * sc, 0.f);
                float d2 = fmaxf(acc[mi][ni][2] * sc, 0.f);
                float d3 = fmaxf(acc[mi][ni][3] * sc, 0.f);
                *(float2*)&Bo[(size_t)r0 * NT + c] = make_float2(d0, d1);
                *(float2*)&Bo[(size_t)(r0 + 8) * NT + c] = make_float2(d2, d3);
                rs[mi][0] += d0 + d1; rs[mi][1] += d2 + d3;
                cs[ni][0] += d0 + d2; cs[ni][1] += d1 + d3;
            }
        }
#pragma unroll
        for (int mi = 0; mi < 4; mi++)
#pragma unroll
            for (int h = 0; h < 2; h++) {
                float v = rs[mi][h];
                v += __shfl_xor_sync(0xffffffffu, v, 1);
                v += __shfl_xor_sync(0xffffffffu, v, 2);
                if (tg == 0) rowacc[wn * 128 + wm * 64 + mi * 16 + g + h * 8] = v;
            }
#pragma unroll
        for (int ni = 0; ni < 4; ni++)
#pragma unroll
            for (int j = 0; j < 2; j++) {
                float v = cs[ni][j];
                v += __shfl_xor_sync(0xffffffffu, v, 4);
                v += __shfl_xor_sync(0xffffffffu, v, 8);
                v += __shfl_xor_sync(0xffffffffu, v, 16);
                if (lane < 4) colacc[wm * 128 + wn * 32 + ni * 8 + tg * 2 + j] = v;
            }
        __syncthreads();
        if (tid < 128) {
            float r = rowacc[tid] + rowacc[128 + tid] + rowacc[256 + tid] + rowacc[384 + tid];
            g_rowpart[(size_t)nt * NB * NT + b * NT + mt * 128 + tid] = r;
            float c = colacc[tid] + colacc[128 + tid];
            g_colpart[(size_t)mt * NB * NT + b * NT + nt * 128 + tid] = c;
        }
    } else {
        int idx = blk - 2048;
        int nx = idx & 1, mt = (idx >> 1) & 127;
        int z3 = idx >> 8;
        size_t arow = (size_t)mt * 128;
        const uint4* Ah = (const uint4*)(z3 ? g_afh : g_vfh) + arow * 32;
        const uint4* Al = (const uint4*)(z3 ? g_afl : g_vfl) + arow * 32;
        int z = z3 ? 3 : 0;
        const uint4* Bh = (const uint4*)g_wth + ((size_t)z * 256 + nx * 128) * 32;
        const uint4* Bl = (const uint4*)g_wtl + ((size_t)z * 256 + nx * 128) * 32;
        float acc[4][4][4] = {};
        gemm128(Ah, Al, Bh, Bl, smem, acc, tid);

        float* Y = z3 ? g_ab2 : g_vb1;
#pragma unroll
        for (int mi = 0; mi < 4; mi++)
#pragma unroll
            for (int h = 0; h < 2; h++) {
                size_t row = arow + wm * 64 + mi * 16 + g + h * 8;
#pragma unroll
                for (int ni = 0; ni < 4; ni++) {
                    int col = nx * 128 + wn * 32 + ni * 8 + tg * 2;
                    float d0 = fmaxf(acc[mi][ni][h * 2 + 0], 0.f);
                    float d1 = fmaxf(acc[mi][ni][h * 2 + 1], 0.f);
                    *(float2*)&Y[row * ND + col] = make_float2(d0, d1);
                }
            }
    }
}

// ================= stage 2b: final sums (+reciprocal colsum) + reset counters =================
__global__ __launch_bounds__(256) void k_sumred() {
    int i = blockIdx.x * 256 + threadIdx.x;
    float r = 0.f, c = 0.f;
#pragma unroll
    for (int t = 0; t < 16; t++) {
        r += g_rowpart[(size_t)t * NB * NT + i];
        c += g_colpart[(size_t)t * NB * NT + i];
    }
    g_rowsum[i] = r;
    g_icolsum[i] = 1.0f / (c + 1e-8f);
    g_ccnt[i] = 0;
}

// ================= stage 3: single-pass beta scan =================
__global__ __launch_bounds__(256) void k_scan(const float* __restrict__ thr_p) {
    int wid = threadIdx.x >> 5, lane = threadIdx.x & 31;
    int row = blockIdx.x * 8 + wid;
    int b = row >> 11, vloc = row & (NT - 1);
    float thr = thr_p[0];
    float invr = 1.0f / (g_rowsum[row] + 1e-8f);
    const float* brow = g_beta + (size_t)row * NT;
    const float* AB2 = g_ab2 + (size_t)b * NT * ND;
    const float* ICS = g_icolsum + b * NT;
    float acc[8] = {};
#pragma unroll
    for (int c8 = 0; c8 < 8; c8++) {
        float v[8];
#pragma unroll
        for (int j = 0; j < 8; j++) v[j] = brow[c8 * 256 + j * 32 + lane];
#pragma unroll
        for (int j = 0; j < 8; j++) {
            int col = c8 * 256 + j * 32 + lane;
            float nvc = v[j] * ICS[col];
            if (nvc > thr) {
                int idx = atomicAdd(&g_ccnt[b * NT + col], 1);
                if (idx < CCAP) {
                    size_t s = (size_t)(b * NT + col) * CCAP + idx;
                    g_cval[s] = nvc;
                    g_cv[s] = vloc;
                }
            }
        }
#pragma unroll
        for (int j = 0; j < 8; j++) {
            float nv = v[j] * invr;
            unsigned m = __ballot_sync(0xffffffffu, nv > thr);
            while (m) {
                int src = __ffs(m) - 1;
                m &= m - 1;
                float val = __shfl_sync(0xffffffffu, nv, src);
                int a = c8 * 256 + j * 32 + src;
#pragma unroll
                for (int q2 = 0; q2 < 8; q2++)
                    acc[q2] = fmaf(val, AB2[(size_t)a * ND + q2 * 32 + lane], acc[q2]);
            }
        }
    }
#pragma unroll
    for (int q2 = 0; q2 < 8; q2++) g_apos[(size_t)row * ND + q2 * 32 + lane] = acc[q2];
}

// ================= fused colmerge + final =================
__global__ __launch_bounds__(256) void k_cfinal(const float* __restrict__ vf, const float* __restrict__ af,
                                                const float* __restrict__ lng, const float* __restrict__ lnb,
                                                float* __restrict__ out) {
    int col = blockIdx.x;
    int b = col >> 11;
    int d = threadIdx.x;
    __shared__ float sval[CCAP];
    __shared__ int   sv[CCAP];
    __shared__ int   scnt;
    if (d == 0) {
        int c = g_ccnt[col]; if (c > CCAP) c = CCAP;
        float tv[CCAP]; int ti[CCAP];
        for (int e = 0; e < c; e++) {
            tv[e] = g_cval[(size_t)col * CCAP + e];
            ti[e] = g_cv[(size_t)col * CCAP + e];
        }
        for (int i = 1; i < c; i++) {
            float fv = tv[i]; int fi = ti[i];
            int j = i - 1;
            while (j >= 0 && ti[j] > fi) { tv[j+1] = tv[j]; ti[j+1] = ti[j]; j--; }
            tv[j+1] = fv; ti[j+1] = fi;
        }
        for (int e = 0; e < c; e++) { sval[e] = tv[e]; sv[e] = ti[e]; }
        scnt = c;
    }
    __syncthreads();
    const float* VB1 = g_vb1 + (size_t)b * NT * ND;
    float vpos = 0.f;
    int c = scnt;
    for (int e = 0; e < c; e++)
        vpos = fmaf(sval[e], VB1[(size_t)sv[e] * ND + d], vpos);

    size_t idx = (size_t)col * ND + d;
    float x1 = vf[idx] + g_apos[idx];
    float x2 = af[idx] + vpos;
    float s1 = x1, q1 = x1 * x1, s2 = x2, q2 = x2 * x2;
#pragma unroll
    for (int o = 16; o; o >>= 1) {
        s1 += __shfl_xor_sync(0xffffffffu, s1, o);
        q1 += __shfl_xor_sync(0xffffffffu, q1, o);
        s2 += __shfl_xor_sync(0xffffffffu, s2, o);
        q2 += __shfl_xor_sync(0xffffffffu, q2, o);
    }
    __shared__ float sh[4][8];
    int w = d >> 5;
    if ((d & 31) == 0) { sh[0][w] = s1; sh[1][w] = q1; sh[2][w] = s2; sh[3][w] = q2; }
    __syncthreads();
    float S1 = 0, Q1 = 0, S2 = 0, Q2 = 0;
#pragma unroll
    for (int i = 0; i < 8; i++) { S1 += sh[0][i]; Q1 += sh[1][i]; S2 += sh[2][i]; Q2 += sh[3][i]; }
    const float invD = 1.0f / 256.0f;
    float mu1 = S1 * invD, mu2 = S2 * invD;
    float r1 = rsqrtf(Q1 * invD - mu1 * mu1 + 1e-6f);
    float r2 = rsqrtf(Q2 * invD - mu2 * mu2 + 1e-6f);
    float gg = lng[d], bb = lnb[d];
    out[idx] = 0.5f * (((x1 - mu1) * r1 * gg + bb) + ((x2 - mu2) * r2 * gg + bb));
}

// ================= launch =================
extern "C" void kernel_launch(void* const* d_in, const int* in_sizes, int n_in,
                              void* d_out, int out_size) {
    (void)in_sizes; (void)n_in; (void)out_size;
    const float* a_fea = (const float*)d_in[0];
    const float* v_fea = (const float*)d_in[1];
    const float* Wv1   = (const float*)d_in[2];
    const float* Wv2   = (const float*)d_in[3];
    const float* Wa1   = (const float*)d_in[4];
    const float* Wa2   = (const float*)d_in[5];
    const float* lng   = (const float*)d_in[6];
    const float* lnb   = (const float*)d_in[7];
    const float* thr   = (const float*)d_in[8];
    float* out = (float*)d_out;

    cudaFuncSetAttribute(k_hmma_s1, cudaFuncAttributeMaxDynamicSharedMemorySize, SMEM_S1);
    cudaFuncSetAttribute(k_fused, cudaFuncAttributeMaxDynamicSharedMemorySize, SMEM_S1);

    k_conv<<<BT * ND / 4 / 256 + 1024, 256>>>((const float4*)v_fea, (const float4*)a_fea,
                                              Wv1, Wv2, Wa1, Wa2);
    k_hmma_s1<<<dim3(2, 128, 2), 256, SMEM_S1>>>();
    k_fused<<<2560, 256, SMEM_S1>>>();
    k_sumred<<<NB * NT / 256, 256>>>();
    k_scan<<<BT / 8, 256>>>(thr);
    k_cfinal<<<BT, 256>>>(v_fea, a_fea, lng, lnb, out);
}

// round 17
// speedup vs baseline: 1.5281x; 1.5281x over previous
#include <cuda_runtime.h>
#include <cuda_bf16.h>
#include <cstdint>

#define NB 8
#define NT 2048
#define ND 256
#define BT (NB*NT)
#define CCAP 12

// ================= scratch (static device globals; no allocation) =================
__device__ __align__(16) float g_vb1[BT*ND];
__device__ __align__(16) float g_ab2[BT*ND];
__device__ __align__(16) __nv_bfloat16 g_vb2h[BT*ND];
__device__ __align__(16) __nv_bfloat16 g_vb2l[BT*ND];
__device__ __align__(16) __nv_bfloat16 g_ab1h[BT*ND];
__device__ __align__(16) __nv_bfloat16 g_ab1l[BT*ND];
__device__ __align__(16) __nv_bfloat16 g_vfh[BT*ND];
__device__ __align__(16) __nv_bfloat16 g_vfl[BT*ND];
__device__ __align__(16) __nv_bfloat16 g_afh[BT*ND];
__device__ __align__(16) __nv_bfloat16 g_afl[BT*ND];
__device__ __align__(16) __nv_bfloat16 g_wth[4*ND*ND];
__device__ __align__(16) __nv_bfloat16 g_wtl[4*ND*ND];
__device__ float g_beta[(size_t)NB*NT*NT];
__device__ float g_rowpart[16*NB*NT];
__device__ float g_colpart[16*NB*NT];
__device__ float g_rowsum[NB*NT];
__device__ float g_icolsum[NB*NT];
__device__ float g_apos[BT*ND];
__device__ int   g_ccnt[NB*NT];
__device__ float g_cval[(size_t)NB*NT*CCAP];
__device__ int   g_cv[(size_t)NB*NT*CCAP];

// ================= PTX helpers =================
__device__ __forceinline__ uint32_t smem_u32(const void* p) {
    uint32_t a;
    asm("{ .reg .u64 t; cvta.to.shared.u64 t, %1; cvt.u32.u64 %0, t; }" : "=r"(a) : "l"(p));
    return a;
}
#define LDMX4(r, addr) \
    asm volatile("ldmatrix.sync.aligned.m8n8.x4.shared.b16 {%0,%1,%2,%3}, [%4];" \
        : "=r"((r)[0]), "=r"((r)[1]), "=r"((r)[2]), "=r"((r)[3]) : "r"(addr))
#define MMA_BF16(d, a, b) \
    asm volatile("mma.sync.aligned.m16n8k16.row.col.f32.bf16.bf16.f32 " \
        "{%0,%1,%2,%3}, {%4,%5,%6,%7}, {%8,%9}, {%0,%1,%2,%3};" \
        : "+f"((d)[0]), "+f"((d)[1]), "+f"((d)[2]), "+f"((d)[3]) \
        : "r"((a)[0]), "r"((a)[1]), "r"((a)[2]), "r"((a)[3]), "r"((b)[0]), "r"((b)[1]))
#define CPA16(dst, src) \
    asm volatile("cp.async.cg.shared.global [%0], [%1], 16;" :: "r"(dst), "l"(src) : "memory")
#define CPA_COMMIT() asm volatile("cp.async.commit_group;" ::: "memory")
#define CPA_WAIT0()  asm volatile("cp.async.wait_group 0;" ::: "memory")

#define ROWB 80
#define ARR_SZ (128*ROWB)
#define OFF_AH 0
#define OFF_AL (1*ARR_SZ)
#define OFF_BH (2*ARR_SZ)
#define OFF_BL (3*ARR_SZ)
#define BUF_SZ (4*ARR_SZ)
#define SMEM_S1 (2*BUF_SZ)   // 81920

// ================= HMMA GEMM core (locked: load-all-fragments-then-MMA) =================
__device__ __forceinline__ void gemm128(
    const uint4* __restrict__ Ah, const uint4* __restrict__ Al,
    const uint4* __restrict__ Bh, const uint4* __restrict__ Bl,
    char* smem, float acc[4][4][4], int tid)
{
    const int lane = tid & 31, wid = tid >> 5;
    const int wm = wid >> 2, wn = wid & 3;
    uint32_t sb = smem_u32(smem);
    const int row0 = tid >> 2, q = tid & 3;
    auto COPY = [&](int kc, int s) {
        uint32_t buf = sb + s * BUF_SZ;
#pragma unroll
        for (int i = 0; i < 2; i++) {
            int r = row0 + i * 64;
            int gi = r * 32 + kc * 4 + q;
            uint32_t so = (uint32_t)r * ROWB + q * 16;
            CPA16(buf + OFF_AH + so, Ah + gi);
            CPA16(buf + OFF_AL + so, Al + gi);
            CPA16(buf + OFF_BH + so, Bh + gi);
            CPA16(buf + OFF_BL + so, Bl + gi);
        }
        CPA_COMMIT();
    };
    COPY(0, 0);
    const int t = lane >> 3, rr = lane & 7;
    uint32_t aoff = sb + (uint32_t)(wm * 64 + (t & 1) * 8 + rr) * ROWB + (t >> 1) * 16;
    uint32_t boff = sb + (uint32_t)(wn * 32 + (t >> 1) * 8 + rr) * ROWB + (t & 1) * 16;
    for (int kc = 0; kc < 8; kc++) {
        CPA_WAIT0();
        __syncthreads();
        if (kc < 7) COPY(kc + 1, (kc + 1) & 1);
        uint32_t bufb = (kc & 1) ? BUF_SZ : 0;
#pragma unroll
        for (int ks = 0; ks < 2; ks++) {
            uint32_t afh[4][4], afl[4][4], bh4[2][4], bl4[2][4];
#pragma unroll
            for (int mi = 0; mi < 4; mi++) {
                uint32_t ad = aoff + bufb + mi * (16 * ROWB) + ks * 32;
                LDMX4(afh[mi], ad + OFF_AH);
                LDMX4(afl[mi], ad + OFF_AL);
            }
#pragma unroll
            for (int n2 = 0; n2 < 2; n2++) {
                uint32_t bd = boff + bufb + n2 * (16 * ROWB) + ks * 32;
                LDMX4(bh4[n2], bd + OFF_BH);
                LDMX4(bl4[n2], bd + OFF_BL);
            }
#pragma unroll
            for (int mi = 0; mi < 4; mi++)
#pragma unroll
                for (int ni = 0; ni < 4; ni++)
                    MMA_BF16(acc[mi][ni], afh[mi], &bh4[ni >> 1][(ni & 1) * 2]);
#pragma unroll
            for (int mi = 0; mi < 4; mi++)
#pragma unroll
                for (int ni = 0; ni < 4; ni++)
                    MMA_BF16(acc[mi][ni], afh[mi], &bl4[ni >> 1][(ni & 1) * 2]);
#pragma unroll
            for (int mi = 0; mi < 4; mi++)
#pragma unroll
                for (int ni = 0; ni < 4; ni++)
                    MMA_BF16(acc[mi][ni], afl[mi], &bh4[ni >> 1][(ni & 1) * 2]);
        }
    }
    __syncthreads();
}

// ================= conversions (merged inputs + weights) =================
__device__ __forceinline__ void split4(float4 v, uint2& hi, uint2& lo) {
    __nv_bfloat16 h0 = __float2bfloat16(v.x), h1 = __float2bfloat16(v.y);
    __nv_bfloat16 h2 = __float2bfloat16(v.z), h3 = __float2bfloat16(v.w);
    __nv_bfloat16 l0 = __float2bfloat16(v.x - __bfloat162float(h0));
    __nv_bfloat16 l1 = __float2bfloat16(v.y - __bfloat162float(h1));
    __nv_bfloat16 l2 = __float2bfloat16(v.z - __bfloat162float(h2));
    __nv_bfloat16 l3 = __float2bfloat16(v.w - __bfloat162float(h3));
    hi.x = (uint32_t)*(uint16_t*)&h0 | ((uint32_t)*(uint16_t*)&h1 << 16);
    hi.y = (uint32_t)*(uint16_t*)&h2 | ((uint32_t)*(uint16_t*)&h3 << 16);
    lo.x = (uint32_t)*(uint16_t*)&l0 | ((uint32_t)*(uint16_t*)&l1 << 16);
    lo.y = (uint32_t)*(uint16_t*)&l2 | ((uint32_t)*(uint16_t*)&l3 << 16);
}

__global__ __launch_bounds__(256) void k_conv(const float4* __restrict__ vf, const float4* __restrict__ af,
                                              const float* __restrict__ W0, const float* __restrict__ W1,
                                              const float* __restrict__ W2, const float* __restrict__ W3) {
    int blk = blockIdx.x;
    if (blk < BT * ND / 4 / 256) {
        int i = blk * 256 + threadIdx.x;
        uint2 h, l;
        split4(vf[i], h, l);
        ((uint2*)g_vfh)[i] = h; ((uint2*)g_vfl)[i] = l;
        split4(af[i], h, l);
        ((uint2*)g_afh)[i] = h; ((uint2*)g_afl)[i] = l;
    } else {
        int wb = blk - BT * ND / 4 / 256;
        int z = wb >> 8;
        int lin = (wb & 255) * 256 + threadIdx.x;
        const float* W = (z == 0) ? W0 : (z == 1) ? W1 : (z == 2) ? W2 : W3;
        int k = lin & 255, n = lin >> 8;
        float v = W[k * 256 + n];
        __nv_bfloat16 h = __float2bfloat16(v);
        __nv_bfloat16 l = __float2bfloat16(v - __bfloat162float(h));
        g_wth[z * 65536 + n * 256 + k] = h;
        g_wtl[z * 65536 + n * 256 + k] = l;
    }
}

// ================= stage 1a: z=1 (vb2) and z=2 (ab1) GEMMs + relu + bf16 split =================
__global__ __launch_bounds__(256, 2) void k_hmma_s1() {
    extern __shared__ char smem[];
    int tid = threadIdx.x;
    int nx = blockIdx.x, mt = blockIdx.y, z = blockIdx.z + 1;   // z in {1,2}
    size_t arow = (size_t)mt * 128;
    const uint4* Ah = (const uint4*)((z == 1) ? g_vfh : g_afh) + arow * 32;
    const uint4* Al = (const uint4*)((z == 1) ? g_vfl : g_afl) + arow * 32;
    const uint4* Bh = (const uint4*)g_wth + ((size_t)z * 256 + nx * 128) * 32;
    const uint4* Bl = (const uint4*)g_wtl + ((size_t)z * 256 + nx * 128) * 32;
    float acc[4][4][4] = {};
    gemm128(Ah, Al, Bh, Bl, smem, acc, tid);

    int lane = tid & 31, wid = tid >> 5, wm = wid >> 2, wn = wid & 3;
    int g = lane >> 2, tg = lane & 3;
    __nv_bfloat16* Yh = (z == 1) ? g_vb2h : g_ab1h;
    __nv_bfloat16* Yl = (z == 1) ? g_vb2l : g_ab1l;
#pragma unroll
    for (int mi = 0; mi < 4; mi++)
#pragma unroll
        for (int h = 0; h < 2; h++) {
            size_t row = arow + wm * 64 + mi * 16 + g + h * 8;
#pragma unroll
            for (int ni = 0; ni < 4; ni++) {
                int col = nx * 128 + wn * 32 + ni * 8 + tg * 2;
                float d0 = fmaxf(acc[mi][ni][h * 2 + 0], 0.f);
                float d1 = fmaxf(acc[mi][ni][h * 2 + 1], 0.f);
                __nv_bfloat16 h0 = __float2bfloat16(d0), h1 = __float2bfloat16(d1);
                __nv_bfloat16 l0 = __float2bfloat16(d0 - __bfloat162float(h0));
                __nv_bfloat16 l1 = __float2bfloat16(d1 - __bfloat162float(h1));
                *(uint32_t*)&Yh[row * ND + col] =
                    (uint32_t)*(uint16_t*)&h0 | ((uint32_t)*(uint16_t*)&h1 << 16);
                *(uint32_t*)&Yl[row * ND + col] =
                    (uint32_t)*(uint16_t*)&l0 | ((uint32_t)*(uint16_t*)&l1 << 16);
            }
        }
}

// ================= fused: beta GEMM (blocks 0..2047) + s1 z=0/3 GEMMs (blocks 2048..2559) =================
__global__ __launch_bounds__(256, 2) void k_fused() {
    extern __shared__ char smem[];
    int tid = threadIdx.x;
    int blk = blockIdx.x;
    int lane = tid & 31, wid = tid >> 5, wm = wid >> 2, wn = wid & 3;
    int g = lane >> 2, tg = lane & 3;

    if (blk < 2048) {
        int nt = blk & 15, mt = (blk >> 4) & 15, b = blk >> 8;
        size_t arow = (size_t)b * NT + mt * 128;
        size_t brow = (size_t)b * NT + nt * 128;
        const uint4* Ah = (const uint4*)g_vb2h + arow * 32;
        const uint4* Al = (const uint4*)g_vb2l + arow * 32;
        const uint4* Bh = (const uint4*)g_ab1h + brow * 32;
        const uint4* Bl = (const uint4*)g_ab1l + brow * 32;
        float acc[4][4][4] = {};
        gemm128(Ah, Al, Bh, Bl, smem, acc, tid);

        float* rowacc = (float*)smem;
        float* colacc = (float*)smem + 512;
        const float sc = 0.0625f;
        float* Bo = g_beta + arow * NT + nt * 128;
        float rs[4][2] = {}, cs[4][2] = {};
#pragma unroll
        for (int mi = 0; mi < 4; mi++) {
            int r0 = wm * 64 + mi * 16 + g;
#pragma unroll
            for (int ni = 0; ni < 4; ni++) {
                int c = wn * 32 + ni * 8 + tg * 2;
                float d0 = fmaxf(acc[mi][ni][0] * sc, 0.f);
                float d1 = fmaxf(acc[mi][ni][1] * sc, 0.f);
                float d2 = fmaxf(acc[mi][ni][2] * sc, 0.f);
                float d3 = fmaxf(acc[mi][ni][3] * sc, 0.f);
                *(float2*)&Bo[(size_t)r0 * NT + c] = make_float2(d0, d1);
                *(float2*)&Bo[(size_t)(r0 + 8) * NT + c] = make_float2(d2, d3);
                rs[mi][0] += d0 + d1; rs[mi][1] += d2 + d3;
                cs[ni][0] += d0 + d2; cs[ni][1] += d1 + d3;
            }
        }
#pragma unroll
        for (int mi = 0; mi < 4; mi++)
#pragma unroll
            for (int h = 0; h < 2; h++) {
                float v = rs[mi][h];
                v += __shfl_xor_sync(0xffffffffu, v, 1);
                v += __shfl_xor_sync(0xffffffffu, v, 2);
                if (tg == 0) rowacc[wn * 128 + wm * 64 + mi * 16 + g + h * 8] = v;
            }
#pragma unroll
        for (int ni = 0; ni < 4; ni++)
#pragma unroll
            for (int j = 0; j < 2; j++) {
                float v = cs[ni][j];
                v += __shfl_xor_sync(0xffffffffu, v, 4);
                v += __shfl_xor_sync(0xffffffffu, v, 8);
                v += __shfl_xor_sync(0xffffffffu, v, 16);
                if (lane < 4) colacc[wm * 128 + wn * 32 + ni * 8 + tg * 2 + j] = v;
            }
        __syncthreads();
        if (tid < 128) {
            float r = rowacc[tid] + rowacc[128 + tid] + rowacc[256 + tid] + rowacc[384 + tid];
            g_rowpart[(size_t)nt * NB * NT + b * NT + mt * 128 + tid] = r;
            float c = colacc[tid] + colacc[128 + tid];
            g_colpart[(size_t)mt * NB * NT + b * NT + nt * 128 + tid] = c;
        }
    } else {
        int idx = blk - 2048;
        int nx = idx & 1, mt = (idx >> 1) & 127;
        int z3 = idx >> 8;
        size_t arow = (size_t)mt * 128;
        const uint4* Ah = (const uint4*)(z3 ? g_afh : g_vfh) + arow * 32;
        const uint4* Al = (const uint4*)(z3 ? g_afl : g_vfl) + arow * 32;
        int z = z3 ? 3 : 0;
        const uint4* Bh = (const uint4*)g_wth + ((size_t)z * 256 + nx * 128) * 32;
        const uint4* Bl = (const uint4*)g_wtl + ((size_t)z * 256 + nx * 128) * 32;
        float acc[4][4][4] = {};
        gemm128(Ah, Al, Bh, Bl, smem, acc, tid);

        float* Y = z3 ? g_ab2 : g_vb1;
#pragma unroll
        for (int mi = 0; mi < 4; mi++)
#pragma unroll
            for (int h = 0; h < 2; h++) {
                size_t row = arow + wm * 64 + mi * 16 + g + h * 8;
#pragma unroll
                for (int ni = 0; ni < 4; ni++) {
                    int col = nx * 128 + wn * 32 + ni * 8 + tg * 2;
                    float d0 = fmaxf(acc[mi][ni][h * 2 + 0], 0.f);
                    float d1 = fmaxf(acc[mi][ni][h * 2 + 1], 0.f);
                    *(float2*)&Y[row * ND + col] = make_float2(d0, d1);
                }
            }
    }
}

// ================= stage 2b: final sums (+reciprocal colsum) + reset counters =================
__global__ __launch_bounds__(256) void k_sumred() {
    int i = blockIdx.x * 256 + threadIdx.x;
    float r = 0.f, c = 0.f;
#pragma unroll
    for (int t = 0; t < 16; t++) {
        r += g_rowpart[(size_t)t * NB * NT + i];
        c += g_colpart[(size_t)t * NB * NT + i];
    }
    g_rowsum[i] = r;
    g_icolsum[i] = 1.0f / (c + 1e-8f);
    g_ccnt[i] = 0;
}

// ================= stage 3: single-pass beta scan =================
__global__ __launch_bounds__(256) void k_scan(const float* __restrict__ thr_p) {
    int wid = threadIdx.x >> 5, lane = threadIdx.x & 31;
    int row = blockIdx.x * 8 + wid;
    int b = row >> 11, vloc = row & (NT - 1);
    float thr = thr_p[0];
    float invr = 1.0f / (g_rowsum[row] + 1e-8f);
    const float* brow = g_beta + (size_t)row * NT;
    const float* AB2 = g_ab2 + (size_t)b * NT * ND;
    const float* ICS = g_icolsum + b * NT;
    float acc[8] = {};
#pragma unroll
    for (int c8 = 0; c8 < 8; c8++) {
        float v[8];
#pragma unroll
        for (int j = 0; j < 8; j++) v[j] = brow[c8 * 256 + j * 32 + lane];
#pragma unroll
        for (int j = 0; j < 8; j++) {
            int col = c8 * 256 + j * 32 + lane;
            float nvc = v[j] * ICS[col];
            if (nvc > thr) {
                int idx = atomicAdd(&g_ccnt[b * NT + col], 1);
                if (idx < CCAP) {
                    size_t s = (size_t)(b * NT + col) * CCAP + idx;
                    g_cval[s] = nvc;
                    g_cv[s] = vloc;
                }
            }
        }
#pragma unroll
        for (int j = 0; j < 8; j++) {
            float nv = v[j] * invr;
            unsigned m = __ballot_sync(0xffffffffu, nv > thr);
            while (m) {
                int src = __ffs(m) - 1;
                m &= m - 1;
                float val = __shfl_sync(0xffffffffu, nv, src);
                int a = c8 * 256 + j * 32 + src;
#pragma unroll
                for (int q2 = 0; q2 < 8; q2++)
                    acc[q2] = fmaf(val, AB2[(size_t)a * ND + q2 * 32 + lane], acc[q2]);
            }
        }
    }
#pragma unroll
    for (int q2 = 0; q2 < 8; q2++) g_apos[(size_t)row * ND + q2 * 32 + lane] = acc[q2];
}

// ================= fused colmerge + final =================
__global__ __launch_bounds__(256) void k_cfinal(const float* __restrict__ vf, const float* __restrict__ af,
                                                const float* __restrict__ lng, const float* __restrict__ lnb,
                                                float* __restrict__ out) {
    int col = blockIdx.x;
    int b = col >> 11;
    int d = threadIdx.x;
    __shared__ float sval[CCAP];
    __shared__ int   sv[CCAP];
    __shared__ int   scnt;
    if (d == 0) {
        int c = g_ccnt[col]; if (c > CCAP) c = CCAP;
        float tv[CCAP]; int ti[CCAP];
        for (int e = 0; e < c; e++) {
            tv[e] = g_cval[(size_t)col * CCAP + e];
            ti[e] = g_cv[(size_t)col * CCAP + e];
        }
        for (int i = 1; i < c; i++) {
            float fv = tv[i]; int fi = ti[i];
            int j = i - 1;
            while (j >= 0 && ti[j] > fi) { tv[j+1] = tv[j]; ti[j+1] = ti[j]; j--; }
            tv[j+1] = fv; ti[j+1] = fi;
        }
        for (int e = 0; e < c; e++) { sval[e] = tv[e]; sv[e] = ti[e]; }
        scnt = c;
    }
    __syncthreads();
    const float* VB1 = g_vb1 + (size_t)b * NT * ND;
    float vpos = 0.f;
    int c = scnt;
    for (int e = 0; e < c; e++)
        vpos = fmaf(sval[e], VB1[(size_t)sv[e] * ND + d], vpos);

    size_t idx = (size_t)col * ND + d;
    float x1 = vf[idx] + g_apos[idx];
    float x2 = af[idx] + vpos;
    float s1 = x1, q1 = x1 * x1, s2 = x2, q2 = x2 * x2;
#pragma unroll
    for (int o = 16; o; o >>= 1) {
        s1 += __shfl_xor_sync(0xffffffffu, s1, o);
        q1 += __shfl_xor_sync(0xffffffffu, q1, o);
        s2 += __shfl_xor_sync(0xffffffffu, s2, o);
        q2 += __shfl_xor_sync(0xffffffffu, q2, o);
    }
    __shared__ float sh[4][8];
    int w = d >> 5;
    if ((d & 31) == 0) { sh[0][w] = s1; sh[1][w] = q1; sh[2][w] = s2; sh[3][w] = q2; }
    __syncthreads();
    float S1 = 0, Q1 = 0, S2 = 0, Q2 = 0;
#pragma unroll
    for (int i = 0; i < 8; i++) { S1 += sh[0][i]; Q1 += sh[1][i]; S2 += sh[2][i]; Q2 += sh[3][i]; }
    const float invD = 1.0f / 256.0f;
    float mu1 = S1 * invD, mu2 = S2 * invD;
    float r1 = rsqrtf(Q1 * invD - mu1 * mu1 + 1e-6f);
    float r2 = rsqrtf(Q2 * invD - mu2 * mu2 + 1e-6f);
    float gg = lng[d], bb = lnb[d];
    out[idx] = 0.5f * (((x1 - mu1) * r1 * gg + bb) + ((x2 - mu2) * r2 * gg + bb));
}

// ================= launch =================
extern "C" void kernel_launch(void* const* d_in, const int* in_sizes, int n_in,
                              void* d_out, int out_size) {
    (void)in_sizes; (void)n_in; (void)out_size;
    const float* a_fea = (const float*)d_in[0];
    const float* v_fea = (const float*)d_in[1];
    const float* Wv1   = (const float*)d_in[2];
    const float* Wv2   = (const float*)d_in[3];
    const float* Wa1   = (const float*)d_in[4];
    const float* Wa2   = (const float*)d_in[5];
    const float* lng   = (const float*)d_in[6];
    const float* lnb   = (const float*)d_in[7];
    const float* thr   = (const float*)d_in[8];
    float* out = (float*)d_out;

    cudaFuncSetAttribute(k_hmma_s1, cudaFuncAttributeMaxDynamicSharedMemorySize, SMEM_S1);
    cudaFuncSetAttribute(k_fused, cudaFuncAttributeMaxDynamicSharedMemorySize, SMEM_S1);

    k_conv<<<BT * ND / 4 / 256 + 1024, 256>>>((const float4*)v_fea, (const float4*)a_fea,
                                              Wv1, Wv2, Wa1, Wa2);
    k_hmma_s1<<<dim3(2, 128, 2), 256, SMEM_S1>>>();
    k_fused<<<2560, 256, SMEM_S1>>>();
    k_sumred<<<NB * NT / 256, 256>>>();
    k_scan<<<BT / 8, 256>>>(thr);
    k_cfinal<<<BT, 256>>>(v_fea, a_fea, lng, lnb, out);
}